// round 13
// baseline (speedup 1.0000x reference)
#include <cuda_runtime.h>
#include <cuda_bf16.h>
#include <math_constants.h>
#include <cstdint>

// GatingNetwork: out = softmax(mask_topk(x @ W^T + b, k=8), axis=-1)
// x: [N=16384, D=4096] f32, W: [E=128, D] f32, b: [E] f32, k=8. out: [N, E] f32.
//
// Round 11: break LDS-phase / MMA-phase alternation (pinned tensor=50% across
// R8-R10) with register double-buffering of B fragments + A raw rows: issue
// ks+1 fragment loads before ks MMA block so crossbar and tensor overlap.
// 256 threads (R8 layout), term-major MMA order, 3xTF32 + two-level fold,
// 4-stage cp.async pipeline, proven top-k/softmax epilogue.

#define NTHREADS 256
#define BM 128
#define BN 128
#define BK 32
#define LSTRIDE 132
#define ASTRIDE 36              // floats per A row in smem (conflict-free frags)

#define NSTAGES 4
#define A_BYTES 18432           // 128 rows * 144 B
#define B_BYTES 32768           // 16KB hi + 16KB lo, fragment-ordered
#define STAGE_BYTES (A_BYTES + B_BYTES)          // 51200
#define SMEM_BYTES (NSTAGES * STAGE_BYTES)       // 204800

// Pre-split, fragment-ordered W: per iter 32KB (16KB hi + 16KB lo)
__device__ __align__(16) unsigned char g_Wfrag[128 * 32768];

__device__ __forceinline__ float to_tf32(float v) {
    float r;
    asm("cvt.rna.tf32.f32 %0, %1;" : "=f"(r) : "f"(v));
    return r;
}
__device__ __forceinline__ uint32_t smem_u32(const void* p) {
    uint32_t a;
    asm("{ .reg .u64 t; cvta.to.shared.u64 t, %1; cvt.u32.u64 %0, t; }"
        : "=r"(a) : "l"(p));
    return a;
}

#define CP_ASYNC16(dst, src) \
    asm volatile("cp.async.cg.shared.global [%0], [%1], 16;" \
                 :: "r"(dst), "l"(src) : "memory")
#define CP_COMMIT() asm volatile("cp.async.commit_group;" ::: "memory")
#define CP_WAIT(n)  asm volatile("cp.async.wait_group %0;" :: "n"(n) : "memory")

#define MMA_TF32(c, a, b) \
    asm volatile("mma.sync.aligned.m16n8k8.row.col.f32.tf32.tf32.f32 " \
        "{%0,%1,%2,%3}, {%4,%5,%6,%7}, {%8,%9}, {%0,%1,%2,%3};" \
        : "+f"((c)[0]), "+f"((c)[1]), "+f"((c)[2]), "+f"((c)[3]) \
        : "r"((a)[0]), "r"((a)[1]), "r"((a)[2]), "r"((a)[3]), \
          "r"((b)[0]), "r"((b)[1]))

__device__ __forceinline__ float warpReduceMax(float v) {
    #pragma unroll
    for (int off = 16; off > 0; off >>= 1)
        v = fmaxf(v, __shfl_xor_sync(0xffffffffu, v, off));
    return v;
}
__device__ __forceinline__ float warpReduceSum(float v) {
    #pragma unroll
    for (int off = 16; off > 0; off >>= 1)
        v += __shfl_xor_sync(0xffffffffu, v, off);
    return v;
}

// ---------------- prep: split W to tf32 hi/lo in B-fragment order ----------------
__global__ void prep_w_kernel(const float* __restrict__ W, int n4, int D) {
    int i = blockIdx.x * blockDim.x + threadIdx.x;
    if (i >= n4) return;
    int d4PerRow = D / 4;
    int e  = i / d4PerRow;
    int d0 = (i - e * d4PerRow) * 4;
    float4 v = reinterpret_cast<const float4*>(W)[i];
    float4 h, l;
    h.x = to_tf32(v.x); l.x = to_tf32(v.x - h.x);
    h.y = to_tf32(v.y); l.y = to_tf32(v.y - h.y);
    h.z = to_tf32(v.z); l.z = to_tf32(v.z - h.z);
    h.w = to_tf32(v.w); l.w = to_tf32(v.w - h.w);
    int it = d0 >> 5;
    int kk = d0 & 31;
    int ks = kk >> 3;
    int chalf = (kk & 7) >> 2;
    int nt = e >> 3;
    int lane0 = (e & 7) * 4;
    size_t base = (size_t)it * 32768;
    unsigned char* pH = g_Wfrag + base;
    unsigned char* pL = g_Wfrag + base + 16384;
    int o = ((ks * 16 + nt) * 32 + lane0) * 8 + chalf * 4;
    *reinterpret_cast<float*>(pH + o)      = h.x;
    *reinterpret_cast<float*>(pH + o + 8)  = h.y;
    *reinterpret_cast<float*>(pH + o + 16) = h.z;
    *reinterpret_cast<float*>(pH + o + 24) = h.w;
    *reinterpret_cast<float*>(pL + o)      = l.x;
    *reinterpret_cast<float*>(pL + o + 8)  = l.y;
    *reinterpret_cast<float*>(pL + o + 16) = l.z;
    *reinterpret_cast<float*>(pL + o + 24) = l.w;
}

// ---------------- main fused kernel ----------------
__global__ __launch_bounds__(NTHREADS, 1)
void gating_mma_kernel(const float* __restrict__ x,
                       const float* __restrict__ bias,
                       const int* __restrict__ kptr,
                       float* __restrict__ out,
                       int N, int D, int E) {
    extern __shared__ char smem[];
    const uint32_t sb = smem_u32(smem);
    const int tid = threadIdx.x;
    const int lane = tid & 31;
    const int wid = tid >> 5;         // 0..7
    const int warpM = wid & 1;        // 0..1  (64 rows each)
    const int warpN = wid >> 1;       // 0..3  (32 cols each)
    const int m0 = blockIdx.x * BM;

    float accT[4][4][4];
    float accC[4][4][4];
    #pragma unroll
    for (int mt = 0; mt < 4; mt++)
        #pragma unroll
        for (int nt = 0; nt < 4; nt++)
            #pragma unroll
            for (int q = 0; q < 4; q++) { accT[mt][nt][q] = 0.0f; accC[mt][nt][q] = 0.0f; }

    const int iters = D / BK;       // 128

    // ---- prologue: fill stages 0..NSTAGES-2 ----
    #pragma unroll
    for (int s = 0; s < NSTAGES - 1; s++) {
        const uint32_t aBase = sb + (uint32_t)s * STAGE_BYTES;
        const uint32_t bBase = aBase + A_BYTES;
        const int k0 = s * BK;
        #pragma unroll
        for (int u = 0; u < 4; u++) {
            int f = tid + u * NTHREADS;
            int row = f >> 3, c4 = f & 7;
            CP_ASYNC16(aBase + (uint32_t)(row * 144 + c4 * 16),
                       &x[(size_t)(m0 + row) * D + k0 + c4 * 4]);
        }
        const unsigned char* wsrc = g_Wfrag + (size_t)s * 32768;
        #pragma unroll
        for (int u = 0; u < 8; u++) {
            int idx = tid + u * NTHREADS;
            CP_ASYNC16(bBase + (uint32_t)(idx * 16), wsrc + (size_t)idx * 16);
        }
        CP_COMMIT();
    }

    for (int it = 0; it < iters; it++) {
        const int stage = it & (NSTAGES - 1);

        if (it < iters - 2)       CP_WAIT(2);
        else if (it == iters - 2) CP_WAIT(1);
        else                      CP_WAIT(0);
        __syncthreads();

        // ---- issue stage it+NSTAGES-1 (safe after barrier) ----
        if (it + NSTAGES - 1 < iters) {
            const int is = it + NSTAGES - 1;
            const uint32_t aBase = sb + (uint32_t)(is & (NSTAGES - 1)) * STAGE_BYTES;
            const uint32_t bBase = aBase + A_BYTES;
            const int k0 = is * BK;
            #pragma unroll
            for (int u = 0; u < 4; u++) {
                int f = tid + u * NTHREADS;
                int row = f >> 3, c4 = f & 7;
                CP_ASYNC16(aBase + (uint32_t)(row * 144 + c4 * 16),
                           &x[(size_t)(m0 + row) * D + k0 + c4 * 4]);
            }
            const unsigned char* wsrc = g_Wfrag + (size_t)is * 32768;
            #pragma unroll
            for (int u = 0; u < 8; u++) {
                int idx = tid + u * NTHREADS;
                CP_ASYNC16(bBase + (uint32_t)(idx * 16), wsrc + (size_t)idx * 16);
            }
            CP_COMMIT();
        }

        // ---- mma phase with register-double-buffered fragment pipeline ----
        const float* aRaw = reinterpret_cast<const float*>(
            smem + (size_t)stage * STAGE_BYTES);
        const char* bB = smem + (size_t)stage * STAGE_BYTES + A_BYTES;

        uint32_t bhP[2][4][2], blP[2][4][2];   // B fragment double buffer
        float    arP[2][4][4];                 // A raw double buffer [buf][mt][e]

        // load ks=0 fragments
        #pragma unroll
        for (int nt = 0; nt < 4; nt++) {
            int ob = ((warpN * 4 + nt) * 32 + lane) * 8;
            uint2 vh = *reinterpret_cast<const uint2*>(bB + ob);
            uint2 vl = *reinterpret_cast<const uint2*>(bB + 16384 + ob);
            bhP[0][nt][0] = vh.x; bhP[0][nt][1] = vh.y;
            blP[0][nt][0] = vl.x; blP[0][nt][1] = vl.y;
        }
        #pragma unroll
        for (int mt = 0; mt < 4; mt++) {
            int r = (warpM * 4 + mt) * 16 + (lane >> 2);
            int i0 = r * ASTRIDE + (lane & 3);
            arP[0][mt][0] = aRaw[i0];
            arP[0][mt][1] = aRaw[i0 + 8 * ASTRIDE];
            arP[0][mt][2] = aRaw[i0 + 4];
            arP[0][mt][3] = aRaw[i0 + 8 * ASTRIDE + 4];
        }

        #pragma unroll
        for (int ks = 0; ks < 4; ks++) {
            const int cur = ks & 1;
            const int nxt = cur ^ 1;
            // ---- prefetch ks+1 fragments BEFORE the MMA block ----
            if (ks < 3) {
                #pragma unroll
                for (int nt = 0; nt < 4; nt++) {
                    int ob = (((ks + 1) * 16 + warpN * 4 + nt) * 32 + lane) * 8;
                    uint2 vh = *reinterpret_cast<const uint2*>(bB + ob);
                    uint2 vl = *reinterpret_cast<const uint2*>(bB + 16384 + ob);
                    bhP[nxt][nt][0] = vh.x; bhP[nxt][nt][1] = vh.y;
                    blP[nxt][nt][0] = vl.x; blP[nxt][nt][1] = vl.y;
                }
                #pragma unroll
                for (int mt = 0; mt < 4; mt++) {
                    int r = (warpM * 4 + mt) * 16 + (lane >> 2);
                    int i0 = r * ASTRIDE + (ks + 1) * 8 + (lane & 3);
                    arP[nxt][mt][0] = aRaw[i0];
                    arP[nxt][mt][1] = aRaw[i0 + 8 * ASTRIDE];
                    arP[nxt][mt][2] = aRaw[i0 + 4];
                    arP[nxt][mt][3] = aRaw[i0 + 8 * ASTRIDE + 4];
                }
            }
            // ---- MMA block for ks (hides the prefetch latency) ----
            #pragma unroll
            for (int mt = 0; mt < 4; mt++) {
                float r0 = arP[cur][mt][0];
                float r1 = arP[cur][mt][1];
                float r2 = arP[cur][mt][2];
                float r3 = arP[cur][mt][3];
                uint32_t ah[4], al[4];
                float h;
                h = to_tf32(r0); ah[0] = __float_as_uint(h); al[0] = __float_as_uint(to_tf32(r0 - h));
                h = to_tf32(r1); ah[1] = __float_as_uint(h); al[1] = __float_as_uint(to_tf32(r1 - h));
                h = to_tf32(r2); ah[2] = __float_as_uint(h); al[2] = __float_as_uint(to_tf32(r2 - h));
                h = to_tf32(r3); ah[3] = __float_as_uint(h); al[3] = __float_as_uint(to_tf32(r3 - h));
                // term-major: same-acc chain distance 4; per-acc order hh->hl->lh
                #pragma unroll
                for (int nt = 0; nt < 4; nt++) MMA_TF32(accC[mt][nt], ah, bhP[cur][nt]);
                #pragma unroll
                for (int nt = 0; nt < 4; nt++) MMA_TF32(accC[mt][nt], ah, blP[cur][nt]);
                #pragma unroll
                for (int nt = 0; nt < 4; nt++) MMA_TF32(accC[mt][nt], al, bhP[cur][nt]);
            }
        }

        // ---- two-level fold every 4 iters (128 K-terms per chunk) ----
        if ((it & 3) == 3) {
            #pragma unroll
            for (int mt = 0; mt < 4; mt++)
                #pragma unroll
                for (int nt = 0; nt < 4; nt++)
                    #pragma unroll
                    for (int q = 0; q < 4; q++) {
                        accT[mt][nt][q] += accC[mt][nt][q];
                        accC[mt][nt][q] = 0.0f;
                    }
        }
    }
    __syncthreads();   // all warps done with last stage before logits overlay

    // ---- epilogue: fragments -> smem logits ----
    float* logits = reinterpret_cast<float*>(smem);
    #pragma unroll
    for (int mt = 0; mt < 4; mt++)
        #pragma unroll
        for (int nt = 0; nt < 4; nt++) {
            int r0 = warpM * 64 + mt * 16 + (lane >> 2);
            int c0 = warpN * 32 + nt * 8 + (lane & 3) * 2;
            logits[r0 * LSTRIDE + c0]           = accT[mt][nt][0];
            logits[r0 * LSTRIDE + c0 + 1]       = accT[mt][nt][1];
            logits[(r0 + 8) * LSTRIDE + c0]     = accT[mt][nt][2];
            logits[(r0 + 8) * LSTRIDE + c0 + 1] = accT[mt][nt][3];
        }
    __syncthreads();

    // ---- per-row top-k threshold + masked softmax (proven R3 epilogue) ----
    const int k = kptr[0];
    float4 bb4 = *reinterpret_cast<const float4*>(&bias[lane * 4]);

    for (int r = wid; r < BM; r += NTHREADS / 32) {
        float4 vv = *reinterpret_cast<const float4*>(&logits[r * LSTRIDE + lane * 4]);
        float vals[4] = {vv.x + bb4.x, vv.y + bb4.y, vv.z + bb4.z, vv.w + bb4.w};
        bool removed[4] = {false, false, false, false};

        float rowMax = -CUDART_INF_F;
        float thr = -CUDART_INF_F;
        for (int itk = 0; itk < k; itk++) {
            float localMax = -CUDART_INF_F;
            #pragma unroll
            for (int j = 0; j < 4; j++)
                if (!removed[j]) localMax = fmaxf(localMax, vals[j]);
            float wmax = warpReduceMax(localMax);
            if (itk == 0) rowMax = wmax;
            thr = wmax;
            unsigned ball = __ballot_sync(0xffffffffu, localMax == wmax);
            int src = __ffs(ball) - 1;
            if (lane == src) {
                #pragma unroll
                for (int j = 0; j < 4; j++) {
                    if (!removed[j] && vals[j] == wmax) { removed[j] = true; break; }
                }
            }
        }

        float ex[4];
        float s = 0.0f;
        #pragma unroll
        for (int j = 0; j < 4; j++) {
            ex[j] = (vals[j] >= thr) ? expf(vals[j] - rowMax) : 0.0f;
            s += ex[j];
        }
        s = warpReduceSum(s);
        float inv = 1.0f / s;
        float4 o = make_float4(ex[0] * inv, ex[1] * inv, ex[2] * inv, ex[3] * inv);
        *reinterpret_cast<float4*>(&out[(size_t)(m0 + r) * E + lane * 4]) = o;
    }
}

extern "C" void kernel_launch(void* const* d_in, const int* in_sizes, int n_in,
                              void* d_out, int out_size) {
    const float* x  = (const float*)d_in[0];
    const float* W  = (const float*)d_in[1];
    const float* b  = (const float*)d_in[2];
    const int*   kp = (const int*)d_in[3];

    int E = in_sizes[2];                 // 128
    int D = in_sizes[1] / E;             // 4096
    int N = in_sizes[0] / D;             // 16384
    float* out = (float*)d_out;

    static bool attrSet = false;
    if (!attrSet) {
        cudaFuncSetAttribute(gating_mma_kernel,
                             cudaFuncAttributeMaxDynamicSharedMemorySize, SMEM_BYTES);
        attrSet = true;
    }

    int n4 = (E * D) / 4;
    prep_w_kernel<<<(n4 + 255) / 256, 256>>>(W, n4, D);

    dim3 grid(N / BM);
    gating_mma_kernel<<<grid, NTHREADS, SMEM_BYTES>>>(x, b, kp, out, N, D, E);
}

// round 14
// speedup vs baseline: 1.6145x; 1.6145x over previous
#include <cuda_runtime.h>
#include <cuda_bf16.h>
#include <math_constants.h>
#include <cstdint>

// GatingNetwork: out = softmax(mask_topk(x @ W^T + b, k=8), axis=-1)
// x: [N=16384, D=4096] f32, W: [E=128, D] f32, b: [E] f32, k=8. out: [N, E] f32.
//
// Round 14: occupancy-driven phase overlap. BM=64 (256 CTAs), 2-stage cp.async,
// 84KB smem/CTA -> 2 CTAs/SM so co-resident CTAs interleave LDS and MMA phases.
// MMA inner loop is the proven R8 code (3xTF32, split-on-load, two-level fold).

#define NTHREADS 256
#define BM 64
#define BN 128
#define BK 32
#define LSTRIDE 132
#define ASTRIDE 36              // floats per A row in smem (conflict-free frags)

#define NSTAGES 2
#define A_BYTES 9216            // 64 rows * 144 B
#define B_BYTES 32768           // 16KB hi + 16KB lo, fragment-ordered
#define STAGE_BYTES (A_BYTES + B_BYTES)          // 41984
#define SMEM_BYTES (NSTAGES * STAGE_BYTES)       // 83968

// Pre-split, fragment-ordered W: per iter 32KB (16KB hi + 16KB lo)
__device__ __align__(16) unsigned char g_Wfrag[128 * 32768];

__device__ __forceinline__ float to_tf32(float v) {
    float r;
    asm("cvt.rna.tf32.f32 %0, %1;" : "=f"(r) : "f"(v));
    return r;
}
__device__ __forceinline__ uint32_t smem_u32(const void* p) {
    uint32_t a;
    asm("{ .reg .u64 t; cvta.to.shared.u64 t, %1; cvt.u32.u64 %0, t; }"
        : "=r"(a) : "l"(p));
    return a;
}

#define CP_ASYNC16(dst, src) \
    asm volatile("cp.async.cg.shared.global [%0], [%1], 16;" \
                 :: "r"(dst), "l"(src) : "memory")
#define CP_COMMIT() asm volatile("cp.async.commit_group;" ::: "memory")
#define CP_WAIT(n)  asm volatile("cp.async.wait_group %0;" :: "n"(n) : "memory")

#define MMA_TF32(c, a, b) \
    asm volatile("mma.sync.aligned.m16n8k8.row.col.f32.tf32.tf32.f32 " \
        "{%0,%1,%2,%3}, {%4,%5,%6,%7}, {%8,%9}, {%0,%1,%2,%3};" \
        : "+f"((c)[0]), "+f"((c)[1]), "+f"((c)[2]), "+f"((c)[3]) \
        : "r"((a)[0]), "r"((a)[1]), "r"((a)[2]), "r"((a)[3]), \
          "r"((b)[0]), "r"((b)[1]))

__device__ __forceinline__ float warpReduceMax(float v) {
    #pragma unroll
    for (int off = 16; off > 0; off >>= 1)
        v = fmaxf(v, __shfl_xor_sync(0xffffffffu, v, off));
    return v;
}
__device__ __forceinline__ float warpReduceSum(float v) {
    #pragma unroll
    for (int off = 16; off > 0; off >>= 1)
        v += __shfl_xor_sync(0xffffffffu, v, off);
    return v;
}

// ---------------- prep: split W to tf32 hi/lo in B-fragment order ----------------
__global__ void prep_w_kernel(const float* __restrict__ W, int n4, int D) {
    int i = blockIdx.x * blockDim.x + threadIdx.x;
    if (i >= n4) return;
    int d4PerRow = D / 4;
    int e  = i / d4PerRow;
    int d0 = (i - e * d4PerRow) * 4;
    float4 v = reinterpret_cast<const float4*>(W)[i];
    float4 h, l;
    h.x = to_tf32(v.x); l.x = to_tf32(v.x - h.x);
    h.y = to_tf32(v.y); l.y = to_tf32(v.y - h.y);
    h.z = to_tf32(v.z); l.z = to_tf32(v.z - h.z);
    h.w = to_tf32(v.w); l.w = to_tf32(v.w - h.w);
    int it = d0 >> 5;
    int kk = d0 & 31;
    int ks = kk >> 3;
    int chalf = (kk & 7) >> 2;
    int nt = e >> 3;
    int lane0 = (e & 7) * 4;
    size_t base = (size_t)it * 32768;
    unsigned char* pH = g_Wfrag + base;
    unsigned char* pL = g_Wfrag + base + 16384;
    int o = ((ks * 16 + nt) * 32 + lane0) * 8 + chalf * 4;
    *reinterpret_cast<float*>(pH + o)      = h.x;
    *reinterpret_cast<float*>(pH + o + 8)  = h.y;
    *reinterpret_cast<float*>(pH + o + 16) = h.z;
    *reinterpret_cast<float*>(pH + o + 24) = h.w;
    *reinterpret_cast<float*>(pL + o)      = l.x;
    *reinterpret_cast<float*>(pL + o + 8)  = l.y;
    *reinterpret_cast<float*>(pL + o + 16) = l.z;
    *reinterpret_cast<float*>(pL + o + 24) = l.w;
}

// ---------------- main fused kernel ----------------
__global__ __launch_bounds__(NTHREADS, 2)
void gating_mma_kernel(const float* __restrict__ x,
                       const float* __restrict__ bias,
                       const int* __restrict__ kptr,
                       float* __restrict__ out,
                       int N, int D, int E) {
    extern __shared__ char smem[];
    const uint32_t sb = smem_u32(smem);
    const int tid = threadIdx.x;
    const int lane = tid & 31;
    const int wid = tid >> 5;         // 0..7
    const int warpM = wid & 1;        // 0..1  (32 rows each)
    const int warpN = wid >> 1;       // 0..3  (32 cols each)
    const int m0 = blockIdx.x * BM;

    float accT[2][4][4];
    float accC[2][4][4];
    #pragma unroll
    for (int mt = 0; mt < 2; mt++)
        #pragma unroll
        for (int nt = 0; nt < 4; nt++)
            #pragma unroll
            for (int q = 0; q < 4; q++) { accT[mt][nt][q] = 0.0f; accC[mt][nt][q] = 0.0f; }

    const int iters = D / BK;       // 128

    // copy slots: A 512 x 16B (f = tid + u*256, u<2): row=f>>3 (0..63), c4=f&7
    //             B 2048 x 16B (idx = tid + u*256, u<8), linear

    // ---- prologue: fill stage 0 ----
    {
        const uint32_t aBase = sb;
        const uint32_t bBase = aBase + A_BYTES;
        #pragma unroll
        for (int u = 0; u < 2; u++) {
            int f = tid + u * NTHREADS;
            int row = f >> 3, c4 = f & 7;
            CP_ASYNC16(aBase + (uint32_t)(row * 144 + c4 * 16),
                       &x[(size_t)(m0 + row) * D + c4 * 4]);
        }
        #pragma unroll
        for (int u = 0; u < 8; u++) {
            int idx = tid + u * NTHREADS;
            CP_ASYNC16(bBase + (uint32_t)(idx * 16), g_Wfrag + (size_t)idx * 16);
        }
        CP_COMMIT();
    }

    for (int it = 0; it < iters; it++) {
        const int stage = it & 1;

        CP_WAIT(0);            // stage `it` complete
        __syncthreads();       // all warps past iter it-1's mma (stage reuse safe)

        // ---- issue stage it+1 into the other buffer ----
        if (it + 1 < iters) {
            const uint32_t aBase = sb + (uint32_t)((it + 1) & 1) * STAGE_BYTES;
            const uint32_t bBase = aBase + A_BYTES;
            const int k0 = (it + 1) * BK;
            #pragma unroll
            for (int u = 0; u < 2; u++) {
                int f = tid + u * NTHREADS;
                int row = f >> 3, c4 = f & 7;
                CP_ASYNC16(aBase + (uint32_t)(row * 144 + c4 * 16),
                           &x[(size_t)(m0 + row) * D + k0 + c4 * 4]);
            }
            const unsigned char* wsrc = g_Wfrag + (size_t)(it + 1) * 32768;
            #pragma unroll
            for (int u = 0; u < 8; u++) {
                int idx = tid + u * NTHREADS;
                CP_ASYNC16(bBase + (uint32_t)(idx * 16), wsrc + (size_t)idx * 16);
            }
            CP_COMMIT();
        }

        // ---- mma phase (R8-proven inner code) ----
        const float* aRaw = reinterpret_cast<const float*>(
            smem + (size_t)stage * STAGE_BYTES);
        const char* bB = smem + (size_t)stage * STAGE_BYTES + A_BYTES;

        #pragma unroll
        for (int ks = 0; ks < 4; ks++) {
            uint32_t bh[4][2], bl[4][2];
            #pragma unroll
            for (int nt = 0; nt < 4; nt++) {
                int ob = ((ks * 16 + warpN * 4 + nt) * 32 + lane) * 8;
                uint2 vh = *reinterpret_cast<const uint2*>(bB + ob);
                uint2 vl = *reinterpret_cast<const uint2*>(bB + 16384 + ob);
                bh[nt][0] = vh.x; bh[nt][1] = vh.y;
                bl[nt][0] = vl.x; bl[nt][1] = vl.y;
            }
            #pragma unroll
            for (int mt = 0; mt < 2; mt++) {
                int r = (warpM * 2 + mt) * 16 + (lane >> 2);
                int i0 = r * ASTRIDE + ks * 8 + (lane & 3);
                float r0 = aRaw[i0];
                float r1 = aRaw[i0 + 8 * ASTRIDE];
                float r2 = aRaw[i0 + 4];
                float r3 = aRaw[i0 + 8 * ASTRIDE + 4];
                uint32_t ah[4], al[4];
                float h;
                h = to_tf32(r0); ah[0] = __float_as_uint(h); al[0] = __float_as_uint(to_tf32(r0 - h));
                h = to_tf32(r1); ah[1] = __float_as_uint(h); al[1] = __float_as_uint(to_tf32(r1 - h));
                h = to_tf32(r2); ah[2] = __float_as_uint(h); al[2] = __float_as_uint(to_tf32(r2 - h));
                h = to_tf32(r3); ah[3] = __float_as_uint(h); al[3] = __float_as_uint(to_tf32(r3 - h));
                #pragma unroll
                for (int nt = 0; nt < 4; nt++) {
                    MMA_TF32(accC[mt][nt], ah, bh[nt]);
                    MMA_TF32(accC[mt][nt], ah, bl[nt]);
                    MMA_TF32(accC[mt][nt], al, bh[nt]);
                }
            }
        }

        // ---- two-level fold every 4 iters (128 K-terms per chunk) ----
        if ((it & 3) == 3) {
            #pragma unroll
            for (int mt = 0; mt < 2; mt++)
                #pragma unroll
                for (int nt = 0; nt < 4; nt++)
                    #pragma unroll
                    for (int q = 0; q < 4; q++) {
                        accT[mt][nt][q] += accC[mt][nt][q];
                        accC[mt][nt][q] = 0.0f;
                    }
        }
    }
    __syncthreads();   // all warps done with last stage before logits overlay

    // ---- epilogue: fragments -> smem logits ----
    float* logits = reinterpret_cast<float*>(smem);
    #pragma unroll
    for (int mt = 0; mt < 2; mt++)
        #pragma unroll
        for (int nt = 0; nt < 4; nt++) {
            int r0 = warpM * 32 + mt * 16 + (lane >> 2);
            int c0 = warpN * 32 + nt * 8 + (lane & 3) * 2;
            logits[r0 * LSTRIDE + c0]           = accT[mt][nt][0];
            logits[r0 * LSTRIDE + c0 + 1]       = accT[mt][nt][1];
            logits[(r0 + 8) * LSTRIDE + c0]     = accT[mt][nt][2];
            logits[(r0 + 8) * LSTRIDE + c0 + 1] = accT[mt][nt][3];
        }
    __syncthreads();

    // ---- per-row top-k threshold + masked softmax (proven R3 epilogue) ----
    const int k = kptr[0];
    float4 bb4 = *reinterpret_cast<const float4*>(&bias[lane * 4]);

    for (int r = wid; r < BM; r += NTHREADS / 32) {
        float4 vv = *reinterpret_cast<const float4*>(&logits[r * LSTRIDE + lane * 4]);
        float vals[4] = {vv.x + bb4.x, vv.y + bb4.y, vv.z + bb4.z, vv.w + bb4.w};
        bool removed[4] = {false, false, false, false};

        float rowMax = -CUDART_INF_F;
        float thr = -CUDART_INF_F;
        for (int itk = 0; itk < k; itk++) {
            float localMax = -CUDART_INF_F;
            #pragma unroll
            for (int j = 0; j < 4; j++)
                if (!removed[j]) localMax = fmaxf(localMax, vals[j]);
            float wmax = warpReduceMax(localMax);
            if (itk == 0) rowMax = wmax;
            thr = wmax;
            unsigned ball = __ballot_sync(0xffffffffu, localMax == wmax);
            int src = __ffs(ball) - 1;
            if (lane == src) {
                #pragma unroll
                for (int j = 0; j < 4; j++) {
                    if (!removed[j] && vals[j] == wmax) { removed[j] = true; break; }
                }
            }
        }

        float ex[4];
        float s = 0.0f;
        #pragma unroll
        for (int j = 0; j < 4; j++) {
            ex[j] = (vals[j] >= thr) ? expf(vals[j] - rowMax) : 0.0f;
            s += ex[j];
        }
        s = warpReduceSum(s);
        float inv = 1.0f / s;
        float4 o = make_float4(ex[0] * inv, ex[1] * inv, ex[2] * inv, ex[3] * inv);
        *reinterpret_cast<float4*>(&out[(size_t)(m0 + r) * E + lane * 4]) = o;
    }
}

extern "C" void kernel_launch(void* const* d_in, const int* in_sizes, int n_in,
                              void* d_out, int out_size) {
    const float* x  = (const float*)d_in[0];
    const float* W  = (const float*)d_in[1];
    const float* b  = (const float*)d_in[2];
    const int*   kp = (const int*)d_in[3];

    int E = in_sizes[2];                 // 128
    int D = in_sizes[1] / E;             // 4096
    int N = in_sizes[0] / D;             // 16384
    float* out = (float*)d_out;

    static bool attrSet = false;
    if (!attrSet) {
        cudaFuncSetAttribute(gating_mma_kernel,
                             cudaFuncAttributeMaxDynamicSharedMemorySize, SMEM_BYTES);
        attrSet = true;
    }

    int n4 = (E * D) / 4;
    prep_w_kernel<<<(n4 + 255) / 256, 256>>>(W, n4, D);

    dim3 grid(N / BM);
    gating_mma_kernel<<<grid, NTHREADS, SMEM_BYTES>>>(x, b, kp, out, N, D, E);
}

// round 15
// speedup vs baseline: 1.9478x; 1.2064x over previous
#include <cuda_runtime.h>
#include <cuda_fp16.h>
#include <cuda_bf16.h>
#include <math_constants.h>
#include <cstdint>

// GatingNetwork: out = softmax(mask_topk(x @ W^T + b, k=8), axis=-1)
// x: [N=16384, D=4096] f32, W: [E=128, D] f32, b: [E] f32, k=8. out: [N, E] f32.
//
// Round 15: fp16x3 decomposition on mma.m16n8k16.f16 (K=16/instr vs tf32 K=8,
// same issue rate, same 11-bit mantissa precision) -> half the MMA instructions
// of 3xTF32. a = ah + al'*2^-12 (ah=fp16(a), al'=fp16((a-ah)*4096)); terms
// C1 += ah*bh ; C2 += ah*bl' + al'*bh ; logit = C1 + C2*2^-12.
// A converted once per tile into fp16 smem arrays; B pre-split+pre-packed.
// Two-level fold every 4 iters. Proven top-k/softmax epilogue.

#define NTHREADS 256
#define BM 64
#define BN 128
#define BK 32
#define LSTRIDE 132

#define NSTAGES 2
#define A_RAW_BYTES 9216        // 64 rows * 144 B (stride 36 floats)
#define B_BYTES 16384           // 8KB bh + 8KB bl', fp16 fragment-ordered
#define STAGE_BYTES (A_RAW_BYTES + B_BYTES)      // 25600
#define CONV_AH 51200           // 64 rows * 20 h2 * 4B = 5120
#define CONV_AL 56320
#define SMEM_BYTES 61440

// Pre-split, fragment-ordered W (fp16): per iter 16KB (8KB hi + 8KB lo*4096)
__device__ __align__(16) unsigned char g_Wfrag[128 * 16384];

__device__ __forceinline__ uint32_t smem_u32(const void* p) {
    uint32_t a;
    asm("{ .reg .u64 t; cvta.to.shared.u64 t, %1; cvt.u32.u64 %0, t; }"
        : "=r"(a) : "l"(p));
    return a;
}

#define CP_ASYNC16(dst, src) \
    asm volatile("cp.async.cg.shared.global [%0], [%1], 16;" \
                 :: "r"(dst), "l"(src) : "memory")
#define CP_COMMIT() asm volatile("cp.async.commit_group;" ::: "memory")
#define CP_WAIT(n)  asm volatile("cp.async.wait_group %0;" :: "n"(n) : "memory")

#define MMA_F16(c, a, b) \
    asm volatile("mma.sync.aligned.m16n8k16.row.col.f32.f16.f16.f32 " \
        "{%0,%1,%2,%3}, {%4,%5,%6,%7}, {%8,%9}, {%0,%1,%2,%3};" \
        : "+f"((c)[0]), "+f"((c)[1]), "+f"((c)[2]), "+f"((c)[3]) \
        : "r"((a)[0]), "r"((a)[1]), "r"((a)[2]), "r"((a)[3]), \
          "r"((b)[0]), "r"((b)[1]))

__device__ __forceinline__ float warpReduceMax(float v) {
    #pragma unroll
    for (int off = 16; off > 0; off >>= 1)
        v = fmaxf(v, __shfl_xor_sync(0xffffffffu, v, off));
    return v;
}
__device__ __forceinline__ float warpReduceSum(float v) {
    #pragma unroll
    for (int off = 16; off > 0; off >>= 1)
        v += __shfl_xor_sync(0xffffffffu, v, off);
    return v;
}

// ---------------- prep: split W to fp16 hi/lo' in m16n8k16 B-fragment order ----
// B fragment (f16, col-major k x n): b0 = {B[k=2c][n], B[k=2c+1][n]} c=lane%4,
// n=lane/4; b1 = same with k+8. Tile (ks16, nt): 32 lanes x 8B.
// Element (e, d): it=d/32, kk=d%32, ks16=kk/16, k16=kk%16, chalf=k16/8,
// kpos=k16%8, lane=4*(e%8)+(kpos/2), nt=e/8.
// Offset in 8KB block: ((ks16*16+nt)*32+lane)*8 + chalf*4 (+2 for odd kpos).
__global__ void prep_w_kernel(const float* __restrict__ W, int n4, int D) {
    int i = blockIdx.x * blockDim.x + threadIdx.x;
    if (i >= n4) return;
    int d4PerRow = D / 4;
    int e  = i / d4PerRow;
    int d0 = (i - e * d4PerRow) * 4;
    float4 v = reinterpret_cast<const float4*>(W)[i];

    __half2 h01 = __float22half2_rn(make_float2(v.x, v.y));
    __half2 h23 = __float22half2_rn(make_float2(v.z, v.w));
    float2 f01 = __half22float2(h01);
    float2 f23 = __half22float2(h23);
    __half2 l01 = __float22half2_rn(make_float2((v.x - f01.x) * 4096.0f,
                                                (v.y - f01.y) * 4096.0f));
    __half2 l23 = __float22half2_rn(make_float2((v.z - f23.x) * 4096.0f,
                                                (v.w - f23.y) * 4096.0f));

    int it = d0 >> 5;
    int kk = d0 & 31;
    int ks16 = kk >> 4;
    int k16 = kk & 15;
    int chalf = k16 >> 3;
    int kpos0 = k16 & 7;                 // 0 or 4 (d0 multiple of 4)
    int nt = e >> 3;
    int L = 4 * (e & 7) + (kpos0 >> 1);  // lane for (kpos0, kpos0+1)

    size_t base = (size_t)it * 16384
                + (size_t)((ks16 * 16 + nt) * 32) * 8 + (size_t)(chalf * 4);
    unsigned char* pH = g_Wfrag + base;
    unsigned char* pL = g_Wfrag + base + 8192;
    *reinterpret_cast<__half2*>(pH + (size_t)L * 8)       = h01;
    *reinterpret_cast<__half2*>(pH + (size_t)(L + 1) * 8) = h23;
    *reinterpret_cast<__half2*>(pL + (size_t)L * 8)       = l01;
    *reinterpret_cast<__half2*>(pL + (size_t)(L + 1) * 8) = l23;
}

// ---------------- main fused kernel ----------------
__global__ __launch_bounds__(NTHREADS, 1)
void gating_mma_kernel(const float* __restrict__ x,
                       const float* __restrict__ bias,
                       const int* __restrict__ kptr,
                       float* __restrict__ out,
                       int N, int D, int E) {
    extern __shared__ char smem[];
    const uint32_t sb = smem_u32(smem);
    const int tid = threadIdx.x;
    const int lane = tid & 31;
    const int wid = tid >> 5;         // 0..7
    const int warpM = wid & 1;        // 0..1  (32 rows each)
    const int warpN = wid >> 1;       // 0..3  (32 cols each)
    const int m0 = blockIdx.x * BM;

    float accT[2][4][4];              // running totals (unscaled)
    float accC1[2][4][4];             // hh chunk
    float accC2[2][4][4];             // (hl + lh) chunk, 4096-scaled
    #pragma unroll
    for (int mt = 0; mt < 2; mt++)
        #pragma unroll
        for (int nt = 0; nt < 4; nt++)
            #pragma unroll
            for (int q = 0; q < 4; q++) {
                accT[mt][nt][q] = 0.0f; accC1[mt][nt][q] = 0.0f; accC2[mt][nt][q] = 0.0f;
            }

    const int iters = D / BK;       // 128
    uint32_t* Ah2u = reinterpret_cast<uint32_t*>(smem + CONV_AH);
    uint32_t* Al2u = reinterpret_cast<uint32_t*>(smem + CONV_AL);

    // ---- prologue: fill stage 0 ----
    {
        #pragma unroll
        for (int u = 0; u < 2; u++) {
            int f = tid + u * NTHREADS;          // 0..511
            int row = f >> 3, c4 = f & 7;
            CP_ASYNC16(sb + (uint32_t)(row * 144 + c4 * 16),
                       &x[(size_t)(m0 + row) * D + c4 * 4]);
        }
        #pragma unroll
        for (int u = 0; u < 4; u++) {
            int idx = tid + u * NTHREADS;        // 0..1023
            CP_ASYNC16(sb + A_RAW_BYTES + (uint32_t)(idx * 16),
                       g_Wfrag + (size_t)idx * 16);
        }
        CP_COMMIT();
    }

    for (int it = 0; it < iters; it++) {
        const int stage = it & 1;
        const uint32_t stOff = (uint32_t)stage * STAGE_BYTES;

        CP_WAIT(0);
        __syncthreads();               // stage ready; prev mma done everywhere

        // ---- issue stage it+1 into the other buffer ----
        if (it + 1 < iters) {
            const uint32_t aBase = sb + (uint32_t)((it + 1) & 1) * STAGE_BYTES;
            const int k0 = (it + 1) * BK;
            #pragma unroll
            for (int u = 0; u < 2; u++) {
                int f = tid + u * NTHREADS;
                int row = f >> 3, c4 = f & 7;
                CP_ASYNC16(aBase + (uint32_t)(row * 144 + c4 * 16),
                           &x[(size_t)(m0 + row) * D + k0 + c4 * 4]);
            }
            const unsigned char* wsrc = g_Wfrag + (size_t)(it + 1) * 16384;
            #pragma unroll
            for (int u = 0; u < 4; u++) {
                int idx = tid + u * NTHREADS;
                CP_ASYNC16(aBase + A_RAW_BYTES + (uint32_t)(idx * 16),
                           wsrc + (size_t)idx * 16);
            }
            CP_COMMIT();
        }

        // ---- conversion pass: raw f32 A -> fp16 hi/lo' arrays (once/tile) ----
        {
            const float* aRaw = reinterpret_cast<const float*>(smem + stOff);
            #pragma unroll
            for (int u = 0; u < 4; u++) {
                int q = tid + u * NTHREADS;      // pair index 0..1023
                int row = q >> 4, p = q & 15;
                float2 v = *reinterpret_cast<const float2*>(aRaw + row * 36 + 2 * p);
                __half2 h = __float22half2_rn(v);
                float2 hf = __half22float2(h);
                __half2 l = __float22half2_rn(make_float2((v.x - hf.x) * 4096.0f,
                                                          (v.y - hf.y) * 4096.0f));
                Ah2u[row * 20 + p] = *reinterpret_cast<uint32_t*>(&h);
                Al2u[row * 20 + p] = *reinterpret_cast<uint32_t*>(&l);
            }
        }
        __syncthreads();

        // ---- mma phase: fp16 m16n8k16, 3 terms ----
        const char* bB = smem + stOff + A_RAW_BYTES;   // bh at +0, bl' at +8192

        #pragma unroll
        for (int ks = 0; ks < 2; ks++) {
            uint32_t bh[4][2], bl[4][2];
            #pragma unroll
            for (int nt = 0; nt < 4; nt++) {
                int ob = ((ks * 16 + warpN * 4 + nt) * 32 + lane) * 8;
                uint2 vh = *reinterpret_cast<const uint2*>(bB + ob);
                uint2 vl = *reinterpret_cast<const uint2*>(bB + 8192 + ob);
                bh[nt][0] = vh.x; bh[nt][1] = vh.y;
                bl[nt][0] = vl.x; bl[nt][1] = vl.y;
            }
            #pragma unroll
            for (int mt = 0; mt < 2; mt++) {
                int row0 = (warpM * 2 + mt) * 16 + (lane >> 2);
                int pi = row0 * 20 + ks * 8 + (lane & 3);
                uint32_t ah[4], al[4];
                ah[0] = Ah2u[pi];           ah[1] = Ah2u[pi + 160];
                ah[2] = Ah2u[pi + 4];       ah[3] = Ah2u[pi + 164];
                al[0] = Al2u[pi];           al[1] = Al2u[pi + 160];
                al[2] = Al2u[pi + 4];       al[3] = Al2u[pi + 164];
                #pragma unroll
                for (int nt = 0; nt < 4; nt++) MMA_F16(accC1[mt][nt], ah, bh[nt]);
                #pragma unroll
                for (int nt = 0; nt < 4; nt++) MMA_F16(accC2[mt][nt], ah, bl[nt]);
                #pragma unroll
                for (int nt = 0; nt < 4; nt++) MMA_F16(accC2[mt][nt], al, bh[nt]);
            }
        }

        // ---- two-level fold every 4 iters (128 K-terms per chunk) ----
        if ((it & 3) == 3) {
            #pragma unroll
            for (int mt = 0; mt < 2; mt++)
                #pragma unroll
                for (int nt = 0; nt < 4; nt++)
                    #pragma unroll
                    for (int q = 0; q < 4; q++) {
                        accT[mt][nt][q] += accC1[mt][nt][q]
                                         + accC2[mt][nt][q] * 2.44140625e-4f;
                        accC1[mt][nt][q] = 0.0f;
                        accC2[mt][nt][q] = 0.0f;
                    }
        }
    }
    __syncthreads();   // all warps done with last stage before logits overlay

    // ---- epilogue: fragments -> smem logits ----
    float* logits = reinterpret_cast<float*>(smem);
    #pragma unroll
    for (int mt = 0; mt < 2; mt++)
        #pragma unroll
        for (int nt = 0; nt < 4; nt++) {
            int r0 = warpM * 32 + mt * 16 + (lane >> 2);
            int c0 = warpN * 32 + nt * 8 + (lane & 3) * 2;
            logits[r0 * LSTRIDE + c0]           = accT[mt][nt][0];
            logits[r0 * LSTRIDE + c0 + 1]       = accT[mt][nt][1];
            logits[(r0 + 8) * LSTRIDE + c0]     = accT[mt][nt][2];
            logits[(r0 + 8) * LSTRIDE + c0 + 1] = accT[mt][nt][3];
        }
    __syncthreads();

    // ---- per-row top-k threshold + masked softmax (proven R3 epilogue) ----
    const int k = kptr[0];
    float4 bb4 = *reinterpret_cast<const float4*>(&bias[lane * 4]);

    for (int r = wid; r < BM; r += NTHREADS / 32) {
        float4 vv = *reinterpret_cast<const float4*>(&logits[r * LSTRIDE + lane * 4]);
        float vals[4] = {vv.x + bb4.x, vv.y + bb4.y, vv.z + bb4.z, vv.w + bb4.w};
        bool removed[4] = {false, false, false, false};

        float rowMax = -CUDART_INF_F;
        float thr = -CUDART_INF_F;
        for (int itk = 0; itk < k; itk++) {
            float localMax = -CUDART_INF_F;
            #pragma unroll
            for (int j = 0; j < 4; j++)
                if (!removed[j]) localMax = fmaxf(localMax, vals[j]);
            float wmax = warpReduceMax(localMax);
            if (itk == 0) rowMax = wmax;
            thr = wmax;
            unsigned ball = __ballot_sync(0xffffffffu, localMax == wmax);
            int src = __ffs(ball) - 1;
            if (lane == src) {
                #pragma unroll
                for (int j = 0; j < 4; j++) {
                    if (!removed[j] && vals[j] == wmax) { removed[j] = true; break; }
                }
            }
        }

        float ex[4];
        float s = 0.0f;
        #pragma unroll
        for (int j = 0; j < 4; j++) {
            ex[j] = (vals[j] >= thr) ? expf(vals[j] - rowMax) : 0.0f;
            s += ex[j];
        }
        s = warpReduceSum(s);
        float inv = 1.0f / s;
        float4 o = make_float4(ex[0] * inv, ex[1] * inv, ex[2] * inv, ex[3] * inv);
        *reinterpret_cast<float4*>(&out[(size_t)(m0 + r) * E + lane * 4]) = o;
    }
}

extern "C" void kernel_launch(void* const* d_in, const int* in_sizes, int n_in,
                              void* d_out, int out_size) {
    const float* x  = (const float*)d_in[0];
    const float* W  = (const float*)d_in[1];
    const float* b  = (const float*)d_in[2];
    const int*   kp = (const int*)d_in[3];

    int E = in_sizes[2];                 // 128
    int D = in_sizes[1] / E;             // 4096
    int N = in_sizes[0] / D;             // 16384
    float* out = (float*)d_out;

    static bool attrSet = false;
    if (!attrSet) {
        cudaFuncSetAttribute(gating_mma_kernel,
                             cudaFuncAttributeMaxDynamicSharedMemorySize, SMEM_BYTES);
        attrSet = true;
    }

    int n4 = (E * D) / 4;
    prep_w_kernel<<<(n4 + 255) / 256, 256>>>(W, n4, D);

    dim3 grid(N / BM);
    gating_mma_kernel<<<grid, NTHREADS, SMEM_BYTES>>>(x, b, kp, out, N, D, E);
}

// round 17
// speedup vs baseline: 2.2104x; 1.1348x over previous
#include <cuda_runtime.h>
#include <cuda_fp16.h>
#include <cuda_bf16.h>
#include <math_constants.h>
#include <cstdint>

// GatingNetwork: out = softmax(mask_topk(x @ W^T + b, k=8), axis=-1)
// x: [N=16384, D=4096] f32, W: [E=128, D] f32, b: [E] f32, k=8. out: [N, E] f32.
//
// Round 17: resubmit of R16 (infra failure, no kernel verdict).
// fp16x3 decomposition on mma.m16n8k16 (R15, 279us) + 2 CTAs/SM via register
// diet: accC2 accumulates continuously (2^-12 scale -> chain error ~2e-10),
// accT (C1 running total) lives in smem [q][tid], touched every 4 iters.
// __launch_bounds__(256,2). Co-resident CTAs overlap convert/LDS and MMA.

#define NTHREADS 256
#define BM 64
#define BN 128
#define BK 32
#define LSTRIDE 132

#define STAGE_BYTES 25600       // 9216 A raw + 16384 B fp16
#define A_RAW_BYTES 9216        // 64 rows * 144 B (stride 36 floats)
#define CONV_AH 51200           // 64 rows * 20 h2-slots * 4B = 5120
#define CONV_AL 56320
#define ACCT_OFF 61440          // 32 q-slots * 256 threads * 4B = 32768
#define SMEM_BYTES 94208

// Pre-split, fragment-ordered W (fp16): per iter 16KB (8KB hi + 8KB lo*4096)
__device__ __align__(16) unsigned char g_Wfrag[128 * 16384];

__device__ __forceinline__ uint32_t smem_u32(const void* p) {
    uint32_t a;
    asm("{ .reg .u64 t; cvta.to.shared.u64 t, %1; cvt.u32.u64 %0, t; }"
        : "=r"(a) : "l"(p));
    return a;
}

#define CP_ASYNC16(dst, src) \
    asm volatile("cp.async.cg.shared.global [%0], [%1], 16;" \
                 :: "r"(dst), "l"(src) : "memory")
#define CP_COMMIT() asm volatile("cp.async.commit_group;" ::: "memory")
#define CP_WAIT(n)  asm volatile("cp.async.wait_group %0;" :: "n"(n) : "memory")

#define MMA_F16(c, a, b) \
    asm volatile("mma.sync.aligned.m16n8k16.row.col.f32.f16.f16.f32 " \
        "{%0,%1,%2,%3}, {%4,%5,%6,%7}, {%8,%9}, {%0,%1,%2,%3};" \
        : "+f"((c)[0]), "+f"((c)[1]), "+f"((c)[2]), "+f"((c)[3]) \
        : "r"((a)[0]), "r"((a)[1]), "r"((a)[2]), "r"((a)[3]), \
          "r"((b)[0]), "r"((b)[1]))

__device__ __forceinline__ float warpReduceMax(float v) {
    #pragma unroll
    for (int off = 16; off > 0; off >>= 1)
        v = fmaxf(v, __shfl_xor_sync(0xffffffffu, v, off));
    return v;
}
__device__ __forceinline__ float warpReduceSum(float v) {
    #pragma unroll
    for (int off = 16; off > 0; off >>= 1)
        v += __shfl_xor_sync(0xffffffffu, v, off);
    return v;
}

// ---------------- prep: split W to fp16 hi/lo' in m16n8k16 B-fragment order ----
__global__ void prep_w_kernel(const float* __restrict__ W, int n4, int D) {
    int i = blockIdx.x * blockDim.x + threadIdx.x;
    if (i >= n4) return;
    int d4PerRow = D / 4;
    int e  = i / d4PerRow;
    int d0 = (i - e * d4PerRow) * 4;
    float4 v = reinterpret_cast<const float4*>(W)[i];

    __half2 h01 = __float22half2_rn(make_float2(v.x, v.y));
    __half2 h23 = __float22half2_rn(make_float2(v.z, v.w));
    float2 f01 = __half22float2(h01);
    float2 f23 = __half22float2(h23);
    __half2 l01 = __float22half2_rn(make_float2((v.x - f01.x) * 4096.0f,
                                                (v.y - f01.y) * 4096.0f));
    __half2 l23 = __float22half2_rn(make_float2((v.z - f23.x) * 4096.0f,
                                                (v.w - f23.y) * 4096.0f));

    int it = d0 >> 5;
    int kk = d0 & 31;
    int ks16 = kk >> 4;
    int k16 = kk & 15;
    int chalf = k16 >> 3;
    int kpos0 = k16 & 7;                 // 0 or 4
    int nt = e >> 3;
    int L = 4 * (e & 7) + (kpos0 >> 1);

    size_t base = (size_t)it * 16384
                + (size_t)((ks16 * 16 + nt) * 32) * 8 + (size_t)(chalf * 4);
    unsigned char* pH = g_Wfrag + base;
    unsigned char* pL = g_Wfrag + base + 8192;
    *reinterpret_cast<__half2*>(pH + (size_t)L * 8)       = h01;
    *reinterpret_cast<__half2*>(pH + (size_t)(L + 1) * 8) = h23;
    *reinterpret_cast<__half2*>(pL + (size_t)L * 8)       = l01;
    *reinterpret_cast<__half2*>(pL + (size_t)(L + 1) * 8) = l23;
}

// ---------------- main fused kernel ----------------
__global__ __launch_bounds__(NTHREADS, 2)
void gating_mma_kernel(const float* __restrict__ x,
                       const float* __restrict__ bias,
                       const int* __restrict__ kptr,
                       float* __restrict__ out,
                       int N, int D, int E) {
    extern __shared__ char smem[];
    const uint32_t sb = smem_u32(smem);
    const int tid = threadIdx.x;
    const int lane = tid & 31;
    const int wid = tid >> 5;         // 0..7
    const int warpM = wid & 1;        // 0..1  (32 rows each)
    const int warpN = wid >> 1;       // 0..3  (32 cols each)
    const int m0 = blockIdx.x * BM;

    float accC1[2][4][4];             // hh chunk (folded to smem every 4 iters)
    float accC2[2][4][4];             // (hl + lh), continuous, 4096-scaled
    #pragma unroll
    for (int mt = 0; mt < 2; mt++)
        #pragma unroll
        for (int nt = 0; nt < 4; nt++)
            #pragma unroll
            for (int q = 0; q < 4; q++) { accC1[mt][nt][q] = 0.0f; accC2[mt][nt][q] = 0.0f; }

    float* accTs = reinterpret_cast<float*>(smem + ACCT_OFF);  // [q32][tid256]
    #pragma unroll
    for (int q = 0; q < 32; q++) accTs[q * NTHREADS + tid] = 0.0f;

    const int iters = D / BK;       // 128
    uint32_t* Ah2u = reinterpret_cast<uint32_t*>(smem + CONV_AH);
    uint32_t* Al2u = reinterpret_cast<uint32_t*>(smem + CONV_AL);

    // ---- prologue: fill stage 0 ----
    {
        #pragma unroll
        for (int u = 0; u < 2; u++) {
            int f = tid + u * NTHREADS;
            int row = f >> 3, c4 = f & 7;
            CP_ASYNC16(sb + (uint32_t)(row * 144 + c4 * 16),
                       &x[(size_t)(m0 + row) * D + c4 * 4]);
        }
        #pragma unroll
        for (int u = 0; u < 4; u++) {
            int idx = tid + u * NTHREADS;
            CP_ASYNC16(sb + A_RAW_BYTES + (uint32_t)(idx * 16),
                       g_Wfrag + (size_t)idx * 16);
        }
        CP_COMMIT();
    }

    for (int it = 0; it < iters; it++) {
        const int stage = it & 1;
        const uint32_t stOff = (uint32_t)stage * STAGE_BYTES;

        CP_WAIT(0);
        __syncthreads();

        // ---- issue stage it+1 ----
        if (it + 1 < iters) {
            const uint32_t aBase = sb + (uint32_t)((it + 1) & 1) * STAGE_BYTES;
            const int k0 = (it + 1) * BK;
            #pragma unroll
            for (int u = 0; u < 2; u++) {
                int f = tid + u * NTHREADS;
                int row = f >> 3, c4 = f & 7;
                CP_ASYNC16(aBase + (uint32_t)(row * 144 + c4 * 16),
                           &x[(size_t)(m0 + row) * D + k0 + c4 * 4]);
            }
            const unsigned char* wsrc = g_Wfrag + (size_t)(it + 1) * 16384;
            #pragma unroll
            for (int u = 0; u < 4; u++) {
                int idx = tid + u * NTHREADS;
                CP_ASYNC16(aBase + A_RAW_BYTES + (uint32_t)(idx * 16),
                           wsrc + (size_t)idx * 16);
            }
            CP_COMMIT();
        }

        // ---- conversion pass: raw f32 A -> fp16 hi/lo' arrays ----
        {
            const float* aRaw = reinterpret_cast<const float*>(smem + stOff);
            #pragma unroll
            for (int u = 0; u < 4; u++) {
                int q = tid + u * NTHREADS;
                int row = q >> 4, p = q & 15;
                float2 v = *reinterpret_cast<const float2*>(aRaw + row * 36 + 2 * p);
                __half2 h = __float22half2_rn(v);
                float2 hf = __half22float2(h);
                __half2 l = __float22half2_rn(make_float2((v.x - hf.x) * 4096.0f,
                                                          (v.y - hf.y) * 4096.0f));
                Ah2u[row * 20 + p] = *reinterpret_cast<uint32_t*>(&h);
                Al2u[row * 20 + p] = *reinterpret_cast<uint32_t*>(&l);
            }
        }
        __syncthreads();

        // ---- mma phase: fp16 m16n8k16, 3 terms ----
        const char* bB = smem + stOff + A_RAW_BYTES;   // bh at +0, bl' at +8192

        #pragma unroll
        for (int ks = 0; ks < 2; ks++) {
            uint32_t bh[4][2], bl[4][2];
            #pragma unroll
            for (int nt = 0; nt < 4; nt++) {
                int ob = ((ks * 16 + warpN * 4 + nt) * 32 + lane) * 8;
                uint2 vh = *reinterpret_cast<const uint2*>(bB + ob);
                uint2 vl = *reinterpret_cast<const uint2*>(bB + 8192 + ob);
                bh[nt][0] = vh.x; bh[nt][1] = vh.y;
                bl[nt][0] = vl.x; bl[nt][1] = vl.y;
            }
            #pragma unroll
            for (int mt = 0; mt < 2; mt++) {
                int row0 = (warpM * 2 + mt) * 16 + (lane >> 2);
                int pi = row0 * 20 + ks * 8 + (lane & 3);
                uint32_t ah[4], al[4];
                ah[0] = Ah2u[pi];           ah[1] = Ah2u[pi + 160];
                ah[2] = Ah2u[pi + 4];       ah[3] = Ah2u[pi + 164];
                al[0] = Al2u[pi];           al[1] = Al2u[pi + 160];
                al[2] = Al2u[pi + 4];       al[3] = Al2u[pi + 164];
                #pragma unroll
                for (int nt = 0; nt < 4; nt++) MMA_F16(accC1[mt][nt], ah, bh[nt]);
                #pragma unroll
                for (int nt = 0; nt < 4; nt++) MMA_F16(accC2[mt][nt], ah, bl[nt]);
                #pragma unroll
                for (int nt = 0; nt < 4; nt++) MMA_F16(accC2[mt][nt], al, bh[nt]);
            }
        }

        // ---- fold C1 chunk into smem total every 4 iters ----
        if ((it & 3) == 3) {
            #pragma unroll
            for (int mt = 0; mt < 2; mt++)
                #pragma unroll
                for (int nt = 0; nt < 4; nt++)
                    #pragma unroll
                    for (int q = 0; q < 4; q++) {
                        int slot = ((mt * 4 + nt) * 4 + q) * NTHREADS + tid;
                        accTs[slot] += accC1[mt][nt][q];
                        accC1[mt][nt][q] = 0.0f;
                    }
        }
    }
    __syncthreads();   // all warps done with last stage

    // ---- combine totals into registers BEFORE logits overlay ----
    float logit[2][4][4];
    #pragma unroll
    for (int mt = 0; mt < 2; mt++)
        #pragma unroll
        for (int nt = 0; nt < 4; nt++)
            #pragma unroll
            for (int q = 0; q < 4; q++) {
                int slot = ((mt * 4 + nt) * 4 + q) * NTHREADS + tid;
                logit[mt][nt][q] = accTs[slot]
                                 + accC2[mt][nt][q] * 2.44140625e-4f;
            }
    __syncthreads();

    // ---- epilogue: fragments -> smem logits ----
    float* logits = reinterpret_cast<float*>(smem);
    #pragma unroll
    for (int mt = 0; mt < 2; mt++)
        #pragma unroll
        for (int nt = 0; nt < 4; nt++) {
            int r0 = warpM * 32 + mt * 16 + (lane >> 2);
            int c0 = warpN * 32 + nt * 8 + (lane & 3) * 2;
            logits[r0 * LSTRIDE + c0]           = logit[mt][nt][0];
            logits[r0 * LSTRIDE + c0 + 1]       = logit[mt][nt][1];
            logits[(r0 + 8) * LSTRIDE + c0]     = logit[mt][nt][2];
            logits[(r0 + 8) * LSTRIDE + c0 + 1] = logit[mt][nt][3];
        }
    __syncthreads();

    // ---- per-row top-k threshold + masked softmax (proven R3 epilogue) ----
    const int k = kptr[0];
    float4 bb4 = *reinterpret_cast<const float4*>(&bias[lane * 4]);

    for (int r = wid; r < BM; r += NTHREADS / 32) {
        float4 vv = *reinterpret_cast<const float4*>(&logits[r * LSTRIDE + lane * 4]);
        float vals[4] = {vv.x + bb4.x, vv.y + bb4.y, vv.z + bb4.z, vv.w + bb4.w};
        bool removed[4] = {false, false, false, false};

        float rowMax = -CUDART_INF_F;
        float thr = -CUDART_INF_F;
        for (int itk = 0; itk < k; itk++) {
            float localMax = -CUDART_INF_F;
            #pragma unroll
            for (int j = 0; j < 4; j++)
                if (!removed[j]) localMax = fmaxf(localMax, vals[j]);
            float wmax = warpReduceMax(localMax);
            if (itk == 0) rowMax = wmax;
            thr = wmax;
            unsigned ball = __ballot_sync(0xffffffffu, localMax == wmax);
            int src = __ffs(ball) - 1;
            if (lane == src) {
                #pragma unroll
                for (int j = 0; j < 4; j++) {
                    if (!removed[j] && vals[j] == wmax) { removed[j] = true; break; }
                }
            }
        }

        float ex[4];
        float s = 0.0f;
        #pragma unroll
        for (int j = 0; j < 4; j++) {
            ex[j] = (vals[j] >= thr) ? expf(vals[j] - rowMax) : 0.0f;
            s += ex[j];
        }
        s = warpReduceSum(s);
        float inv = 1.0f / s;
        float4 o = make_float4(ex[0] * inv, ex[1] * inv, ex[2] * inv, ex[3] * inv);
        *reinterpret_cast<float4*>(&out[(size_t)(m0 + r) * E + lane * 4]) = o;
    }
}

extern "C" void kernel_launch(void* const* d_in, const int* in_sizes, int n_in,
                              void* d_out, int out_size) {
    const float* x  = (const float*)d_in[0];
    const float* W  = (const float*)d_in[1];
    const float* b  = (const float*)d_in[2];
    const int*   kp = (const int*)d_in[3];

    int E = in_sizes[2];                 // 128
    int D = in_sizes[1] / E;             // 4096
    int N = in_sizes[0] / D;             // 16384
    float* out = (float*)d_out;

    static bool attrSet = false;
    if (!attrSet) {
        cudaFuncSetAttribute(gating_mma_kernel,
                             cudaFuncAttributeMaxDynamicSharedMemorySize, SMEM_BYTES);
        attrSet = true;
    }

    int n4 = (E * D) / 4;
    prep_w_kernel<<<(n4 + 255) / 256, 256>>>(W, n4, D);

    dim3 grid(N / BM);
    gating_mma_kernel<<<grid, NTHREADS, SMEM_BYTES>>>(x, b, kp, out, N, D, E);
}